// round 10
// baseline (speedup 1.0000x reference)
#include <cuda_runtime.h>
#include <cuda_bf16.h>

// out[b, i] = x[b, i] * weight[i] + bias[i]
// BATCH = 8192, IN_SIZE = 4096, fp32. HBM-bound.
//
// CONVERGED FINAL (R2 shape; best of 9 measured variants, reproduced):
//  - 35.84us kernel / 43.52us bench, DRAM 75.0%, 5945 GB/s active;
//    268 MB compulsory traffic / 35.84us = 7.48 TB/s = 93.5% of spec.
//    Residual is 1:1 R/W bus-turnaround -> at roofline.
//  - block = 256 threads, fixed strip of 256 float4 columns
//    (w/b loaded once per thread into registers -> inner work is 1 LDG + 1 STG)
//  - 4 rows per block, all 4 LDG.128 front-batched (MLP_p1 = 4)
//  - __ldcs/__stcs streaming hints; grid = (4, 2048) = 8192 CTAs, no tail
//  - 32 regs -> ~79% occupancy; best latency-coverage/occupancy balance
//  Measured flat alternatives: MLP 1/8, persistent single-wave (regression),
//  LDG.256, write-back stores, L2 evict_last pinning.

static constexpr int IN_SIZE   = 4096;
static constexpr int IN_SIZE4  = IN_SIZE / 4;        // 1024 float4 per row
static constexpr int THREADS   = 256;
static constexpr int COL_GRPS  = IN_SIZE4 / THREADS; // 4
static constexpr int ROWS_PER_BLOCK = 4;

__global__ __launch_bounds__(THREADS)
void diag_linear_kernel(const float4* __restrict__ x4,
                        const float4* __restrict__ w4,
                        const float4* __restrict__ b4,
                        float4* __restrict__ out4)
{
    const int col4 = blockIdx.x * THREADS + threadIdx.x;      // 0..1023
    const int row0 = blockIdx.y * ROWS_PER_BLOCK;

    // Per-thread constants: loaded once, L1/L2-resident table (16 KB each)
    const float4 wv = __ldg(&w4[col4]);
    const float4 bv = __ldg(&b4[col4]);

    const long base = (long)row0 * IN_SIZE4 + col4;

    // Front-batched loads: 4 independent LDG.128 in flight
    float4 v0 = __ldcs(&x4[base + 0L * IN_SIZE4]);
    float4 v1 = __ldcs(&x4[base + 1L * IN_SIZE4]);
    float4 v2 = __ldcs(&x4[base + 2L * IN_SIZE4]);
    float4 v3 = __ldcs(&x4[base + 3L * IN_SIZE4]);

    v0.x = fmaf(v0.x, wv.x, bv.x); v0.y = fmaf(v0.y, wv.y, bv.y);
    v0.z = fmaf(v0.z, wv.z, bv.z); v0.w = fmaf(v0.w, wv.w, bv.w);

    v1.x = fmaf(v1.x, wv.x, bv.x); v1.y = fmaf(v1.y, wv.y, bv.y);
    v1.z = fmaf(v1.z, wv.z, bv.z); v1.w = fmaf(v1.w, wv.w, bv.w);

    v2.x = fmaf(v2.x, wv.x, bv.x); v2.y = fmaf(v2.y, wv.y, bv.y);
    v2.z = fmaf(v2.z, wv.z, bv.z); v2.w = fmaf(v2.w, wv.w, bv.w);

    v3.x = fmaf(v3.x, wv.x, bv.x); v3.y = fmaf(v3.y, wv.y, bv.y);
    v3.z = fmaf(v3.z, wv.z, bv.z); v3.w = fmaf(v3.w, wv.w, bv.w);

    __stcs(&out4[base + 0L * IN_SIZE4], v0);
    __stcs(&out4[base + 1L * IN_SIZE4], v1);
    __stcs(&out4[base + 2L * IN_SIZE4], v2);
    __stcs(&out4[base + 3L * IN_SIZE4], v3);
}

extern "C" void kernel_launch(void* const* d_in, const int* in_sizes, int n_in,
                              void* d_out, int out_size)
{
    const float* x      = (const float*)d_in[0];
    const float* weight = (const float*)d_in[1];
    const float* bias   = (const float*)d_in[2];
    float* out          = (float*)d_out;

    const int n    = in_sizes[0];            // BATCH * IN_SIZE
    const int rows = n / IN_SIZE;            // 8192

    dim3 grid(COL_GRPS, rows / ROWS_PER_BLOCK);   // (4, 2048) = 8192 CTAs
    diag_linear_kernel<<<grid, THREADS>>>(
        (const float4*)x, (const float4*)weight, (const float4*)bias,
        (float4*)out);
}

// round 11
// speedup vs baseline: 1.0287x; 1.0287x over previous
#include <cuda_runtime.h>
#include <cuda_bf16.h>

// out[b, i] = x[b, i] * weight[i] + bias[i]
// BATCH = 8192, IN_SIZE = 4096, fp32. HBM-bound.
//
// CONVERGED FINAL (R2 shape; best of 11 samples across 7 distinct designs):
//  - kernel 35.84-36.22us, DRAM 73.8-75.0%, ~5.9 TB/s active;
//    268 MB compulsory / 35.84us = 7.48 TB/s = 93.5% of 8 TB/s spec.
//    Residual = 1:1 R/W bus-turnaround -> at roofline. Bench deltas beyond
//    this are harness jitter (43.5us floor observed twice with this exact file).
//  - block = 256 threads, fixed strip of 256 float4 columns
//    (w/b loaded once per thread into registers -> inner work is 1 LDG + 1 STG)
//  - 4 rows per block, all 4 LDG.128 front-batched (MLP_p1 = 4)
//  - __ldcs/__stcs streaming hints; grid = (4, 2048) = 8192 CTAs, no tail
//  - 32 regs -> ~78% occupancy
//  Measured flat/worse: MLP 1/8, persistent single-wave, LDG.256,
//  write-back stores, L2 evict_last pinning.

static constexpr int IN_SIZE   = 4096;
static constexpr int IN_SIZE4  = IN_SIZE / 4;        // 1024 float4 per row
static constexpr int THREADS   = 256;
static constexpr int COL_GRPS  = IN_SIZE4 / THREADS; // 4
static constexpr int ROWS_PER_BLOCK = 4;

__global__ __launch_bounds__(THREADS)
void diag_linear_kernel(const float4* __restrict__ x4,
                        const float4* __restrict__ w4,
                        const float4* __restrict__ b4,
                        float4* __restrict__ out4)
{
    const int col4 = blockIdx.x * THREADS + threadIdx.x;      // 0..1023
    const int row0 = blockIdx.y * ROWS_PER_BLOCK;

    // Per-thread constants: loaded once, L1/L2-resident table (16 KB each)
    const float4 wv = __ldg(&w4[col4]);
    const float4 bv = __ldg(&b4[col4]);

    const long base = (long)row0 * IN_SIZE4 + col4;

    // Front-batched loads: 4 independent LDG.128 in flight
    float4 v0 = __ldcs(&x4[base + 0L * IN_SIZE4]);
    float4 v1 = __ldcs(&x4[base + 1L * IN_SIZE4]);
    float4 v2 = __ldcs(&x4[base + 2L * IN_SIZE4]);
    float4 v3 = __ldcs(&x4[base + 3L * IN_SIZE4]);

    v0.x = fmaf(v0.x, wv.x, bv.x); v0.y = fmaf(v0.y, wv.y, bv.y);
    v0.z = fmaf(v0.z, wv.z, bv.z); v0.w = fmaf(v0.w, wv.w, bv.w);

    v1.x = fmaf(v1.x, wv.x, bv.x); v1.y = fmaf(v1.y, wv.y, bv.y);
    v1.z = fmaf(v1.z, wv.z, bv.z); v1.w = fmaf(v1.w, wv.w, bv.w);

    v2.x = fmaf(v2.x, wv.x, bv.x); v2.y = fmaf(v2.y, wv.y, bv.y);
    v2.z = fmaf(v2.z, wv.z, bv.z); v2.w = fmaf(v2.w, wv.w, bv.w);

    v3.x = fmaf(v3.x, wv.x, bv.x); v3.y = fmaf(v3.y, wv.y, bv.y);
    v3.z = fmaf(v3.z, wv.z, bv.z); v3.w = fmaf(v3.w, wv.w, bv.w);

    __stcs(&out4[base + 0L * IN_SIZE4], v0);
    __stcs(&out4[base + 1L * IN_SIZE4], v1);
    __stcs(&out4[base + 2L * IN_SIZE4], v2);
    __stcs(&out4[base + 3L * IN_SIZE4], v3);
}

extern "C" void kernel_launch(void* const* d_in, const int* in_sizes, int n_in,
                              void* d_out, int out_size)
{
    const float* x      = (const float*)d_in[0];
    const float* weight = (const float*)d_in[1];
    const float* bias   = (const float*)d_in[2];
    float* out          = (float*)d_out;

    const int n    = in_sizes[0];            // BATCH * IN_SIZE
    const int rows = n / IN_SIZE;            // 8192

    dim3 grid(COL_GRPS, rows / ROWS_PER_BLOCK);   // (4, 2048) = 8192 CTAs
    diag_linear_kernel<<<grid, THREADS>>>(
        (const float4*)x, (const float4*)weight, (const float4*)bias,
        (float4*)out);
}